// round 6
// baseline (speedup 1.0000x reference)
#include <cuda_runtime.h>
#include <cuda_bf16.h>
#include <cstdint>

// CenterLoss: out = mean_i clamp(||x[i] - centers[labels[i]]||^2, 1e-12, 1e12)
// x: (16384, 2048) f32, labels: (16384,) int32 (harness narrows int64->int32),
// centers: (751, 2048) f32
// Inputs per metadata order: d_in[0]=x, d_in[1]=labels, d_in[2]=centers.

#define B_ROWS 16384
#define D_DIM  2048
#define D_VEC  (D_DIM / 4)            // 512 float4 per row
#define TPB    128                    // threads per block (row kernel)
#define ROWS_PER_CTA 2
#define NUM_CTAS (B_ROWS / ROWS_PER_CTA)
#define F4_PER_THREAD (D_VEC / TPB)   // 4 float4 per row per thread

__device__ float g_partial[B_ROWS];

// Streaming (evict-first) float4 load: keeps the one-pass x stream from
// evicting the heavily-reused centers working set (6.2 MB) out of L2.
__device__ __forceinline__ float4 ldcs_f4(const float4* p) {
    float4 v;
    asm volatile("ld.global.cs.v4.f32 {%0,%1,%2,%3}, [%4];"
                 : "=f"(v.x), "=f"(v.y), "=f"(v.z), "=f"(v.w)
                 : "l"(p));
    return v;
}

__global__ __launch_bounds__(TPB) void row_dist_kernel(
    const float4* __restrict__ x,
    const int* __restrict__ labels,
    const float4* __restrict__ centers)
{
    const int row0 = blockIdx.x * ROWS_PER_CTA;
    const int row1 = row0 + 1;
    const int t = threadIdx.x;

    const float4* __restrict__ xr0 = x + (size_t)row0 * D_VEC;
    const float4* __restrict__ xr1 = x + (size_t)row1 * D_VEC;
    const int lab0 = labels[row0];
    const int lab1 = labels[row1];
    const float4* __restrict__ cr0 = centers + (size_t)lab0 * D_VEC;
    const float4* __restrict__ cr1 = centers + (size_t)lab1 * D_VEC;

    // Front-batch 16 independent LDG.128 per thread:
    // 8 x-stream loads (2 rows x 4) + 8 centers loads (2 rows x 4).
    float4 a0[F4_PER_THREAD], a1[F4_PER_THREAD];
    float4 b0[F4_PER_THREAD], b1[F4_PER_THREAD];
    #pragma unroll
    for (int i = 0; i < F4_PER_THREAD; i++) a0[i] = ldcs_f4(&xr0[t + i * TPB]);
    #pragma unroll
    for (int i = 0; i < F4_PER_THREAD; i++) a1[i] = ldcs_f4(&xr1[t + i * TPB]);
    #pragma unroll
    for (int i = 0; i < F4_PER_THREAD; i++) b0[i] = __ldg(&cr0[t + i * TPB]);
    #pragma unroll
    for (int i = 0; i < F4_PER_THREAD; i++) b1[i] = __ldg(&cr1[t + i * TPB]);

    float acc0 = 0.0f, acc1 = 0.0f;
    #pragma unroll
    for (int i = 0; i < F4_PER_THREAD; i++) {
        float d;
        d = a0[i].x - b0[i].x; acc0 = fmaf(d, d, acc0);
        d = a0[i].y - b0[i].y; acc0 = fmaf(d, d, acc0);
        d = a0[i].z - b0[i].z; acc0 = fmaf(d, d, acc0);
        d = a0[i].w - b0[i].w; acc0 = fmaf(d, d, acc0);
        d = a1[i].x - b1[i].x; acc1 = fmaf(d, d, acc1);
        d = a1[i].y - b1[i].y; acc1 = fmaf(d, d, acc1);
        d = a1[i].z - b1[i].z; acc1 = fmaf(d, d, acc1);
        d = a1[i].w - b1[i].w; acc1 = fmaf(d, d, acc1);
    }

    // Warp reduce both rows
    #pragma unroll
    for (int off = 16; off > 0; off >>= 1) {
        acc0 += __shfl_down_sync(0xFFFFFFFFu, acc0, off);
        acc1 += __shfl_down_sync(0xFFFFFFFFu, acc1, off);
    }

    // Block reduce across 4 warps, both rows
    __shared__ float warp_sums0[TPB / 32];
    __shared__ float warp_sums1[TPB / 32];
    const int wid = t >> 5;
    const int lid = t & 31;
    if (lid == 0) { warp_sums0[wid] = acc0; warp_sums1[wid] = acc1; }
    __syncthreads();

    if (wid == 0) {
        float v0 = (lid < TPB / 32) ? warp_sums0[lid] : 0.0f;
        float v1 = (lid < TPB / 32) ? warp_sums1[lid] : 0.0f;
        #pragma unroll
        for (int off = 2; off > 0; off >>= 1) {
            v0 += __shfl_down_sync(0xFFFFFFFFu, v0, off);
            v1 += __shfl_down_sync(0xFFFFFFFFu, v1, off);
        }
        if (lid == 0) {
            // clamp per-row before the mean (matches reference semantics)
            v0 = fminf(fmaxf(v0, 1e-12f), 1e12f);
            v1 = fminf(fmaxf(v1, 1e-12f), 1e12f);
            g_partial[row0] = v0;
            g_partial[row1] = v1;
        }
    }
}

#define RED_TPB 1024

__global__ __launch_bounds__(RED_TPB) void final_reduce_kernel(float* __restrict__ out)
{
    const int t = threadIdx.x;
    float acc = 0.0f;
    // 16384 / 1024 = 16 values per thread, fixed order -> deterministic
    #pragma unroll
    for (int i = 0; i < B_ROWS / RED_TPB; i++)
        acc += g_partial[t + i * RED_TPB];

    #pragma unroll
    for (int off = 16; off > 0; off >>= 1)
        acc += __shfl_down_sync(0xFFFFFFFFu, acc, off);

    __shared__ float warp_sums[RED_TPB / 32];
    const int wid = t >> 5;
    const int lid = t & 31;
    if (lid == 0) warp_sums[wid] = acc;
    __syncthreads();

    if (wid == 0) {
        float v = (lid < RED_TPB / 32) ? warp_sums[lid] : 0.0f;
        #pragma unroll
        for (int off = 16; off > 0; off >>= 1)
            v += __shfl_down_sync(0xFFFFFFFFu, v, off);
        if (lid == 0)
            out[0] = v * (1.0f / (float)B_ROWS);
    }
}

extern "C" void kernel_launch(void* const* d_in, const int* in_sizes, int n_in,
                              void* d_out, int out_size)
{
    const float4* x       = (const float4*)d_in[0];
    const int*    labels  = (const int*)d_in[1];
    const float4* centers = (const float4*)d_in[2];
    float*        out     = (float*)d_out;

    row_dist_kernel<<<NUM_CTAS, TPB>>>(x, labels, centers);
    final_reduce_kernel<<<1, RED_TPB>>>(out);
}